// round 7
// baseline (speedup 1.0000x reference)
#include <cuda_runtime.h>
#include <cuda_bf16.h>
#include <cstdint>

#define B_ 8
#define N_ 512
#define T_ 128
#define H_ 8

#define NTILES 4096        // tile = 128 rows (all t for one (b,n)) x 128 cols
#define GRID_GEMM 152
#define ROWB 272           // padded row stride (bytes) -> conflict-free ldmatrix
#define IMS 34816          // one 128x128 bf16 image = 128*272 bytes

// -------- scratch (device globals: allocation-free) --------
__device__ float g_hp[(size_t)B_ * N_ * T_ * 128];      // [b][n][t][e]
__device__ float g_sj[(size_t)B_ * N_ * T_ * H_];       // [b][n][t][h]
__device__ float g_s0[B_ * T_ * H_];                    // [b][t][h]
__device__ __align__(16) __nv_bfloat16 g_Whi[16384];    // W1^T hi, [e][k]
__device__ __align__(16) __nv_bfloat16 g_Wlo[16384];    // W1^T lo, [e][k]

// ---------------- helpers ----------------
__device__ __forceinline__ uint32_t smem_u32(const void* p) {
    uint32_t a;
    asm("{ .reg .u64 t; cvta.to.shared.u64 t, %1; cvt.u32.u64 %0, t; }" : "=r"(a) : "l"(p));
    return a;
}
__device__ __forceinline__ void ldsm4(uint32_t* r, uint32_t addr) {
    asm volatile("ldmatrix.sync.aligned.m8n8.x4.shared.b16 {%0,%1,%2,%3}, [%4];"
                 : "=r"(r[0]), "=r"(r[1]), "=r"(r[2]), "=r"(r[3]) : "r"(addr));
}
__device__ __forceinline__ void mma_bf16(float* c, const uint32_t* a,
                                         uint32_t b0, uint32_t b1) {
    asm volatile(
        "mma.sync.aligned.m16n8k16.row.col.f32.bf16.bf16.f32 "
        "{%0,%1,%2,%3}, {%4,%5,%6,%7}, {%8,%9}, {%0,%1,%2,%3};"
        : "+f"(c[0]), "+f"(c[1]), "+f"(c[2]), "+f"(c[3])
        : "r"(a[0]), "r"(a[1]), "r"(a[2]), "r"(a[3]), "r"(b0), "r"(b1));
}
__device__ __forceinline__ uint32_t pk_bf(float a, float b) {  // lo-half=a, hi-half=b
    uint32_t r;
    asm("cvt.rn.bf16x2.f32 %0, %1, %2;" : "=r"(r) : "f"(b), "f"(a));
    return r;
}
__device__ __forceinline__ float bf_round(float x) {
    return __bfloat162float(__float2bfloat16(x));
}

// ===================== k_prep: W1 -> W^T hi/lo bf16 images =====================
__global__ void k_prep(const float* __restrict__ W1) {
    int idx = blockIdx.x * 256 + threadIdx.x;   // e*128 + k
    int e = idx >> 7, k = idx & 127;
    float w = W1[k * 128 + e];
    float hf = bf_round(w);
    g_Whi[idx] = __float2bfloat16(w);
    g_Wlo[idx] = __float2bfloat16(w - hf);
}

// ===================== k_gemm: persistent mma.sync split-bf16 GEMM =====================
// smem: Whi@0, Wlo@IMS, A[buf][hi/lo]@69632+buf*2*IMS(+IMS), b1@208896, Wa@209408
#define SM_A     69632
#define SM_B1    208896
#define SM_WA    209408
#define SMEM_TOTAL 209536

__global__ __launch_bounds__(512, 1) void k_gemm(
    const float* __restrict__ h, const float* __restrict__ b1,
    const float* __restrict__ Wa)
{
    extern __shared__ char smem[];
    const uint32_t sb = smem_u32(smem);
    const int tid = threadIdx.x, wid = tid >> 5, l = tid & 31;
    const int wr = wid >> 2, wc = wid & 3;     // warp grid 4x4: 32 rows x 32 cols each

    // ---- one-time: W images + consts into smem ----
    {
        const uint4* sh = reinterpret_cast<const uint4*>(g_Whi);
        const uint4* sl = reinterpret_cast<const uint4*>(g_Wlo);
        #pragma unroll
        for (int p = 0; p < 4; ++p) {
            int q = tid + p * 512;             // 2048 16B chunks per image
            int row = q >> 4, c = q & 15;
            *reinterpret_cast<uint4*>(smem + row * ROWB + c * 16) = sh[q];
            *reinterpret_cast<uint4*>(smem + IMS + row * ROWB + c * 16) = sl[q];
        }
    }
    if (tid < 128) ((float*)(smem + SM_B1))[tid] = b1[tid];
    if (tid >= 480) ((float*)(smem + SM_WA))[tid - 480] = Wa[tid - 480];

    const float* b1s = (const float*)(smem + SM_B1);
    const float* waS = (const float*)(smem + SM_WA);

    // per-lane ldmatrix offsets
    const uint32_t a_lane = (uint32_t)((l & 15) * ROWB + (l >> 4) * 16);
    const uint32_t b_lane = (uint32_t)(((l >> 4) * 8 + (l & 7)) * ROWB + ((l >> 3) & 1) * 16);
    const uint32_t a_warp = (uint32_t)(wr * 32) * ROWB;
    const uint32_t b_warp = (uint32_t)(wc * 32) * ROWB;

    const int tstart = blockIdx.x, tstep = gridDim.x;
    const int nlocal = (NTILES - tstart + tstep - 1) / tstep;

    auto ldg_chunk = [&](int tile, int c, float4* rg) {
        const float4* hg = reinterpret_cast<const float4*>(h + (size_t)tile * 16384);
        #pragma unroll
        for (int p = 0; p < 4; ++p) rg[p] = hg[c * 2048 + tid + p * 512];
    };
    auto sts_chunk = [&](int buf, int c, const float4* rg) {
        char* Ahi = smem + SM_A + buf * (2 * IMS);
        char* Alo = Ahi + IMS;
        #pragma unroll
        for (int p = 0; p < 4; ++p) {
            int q = c * 2048 + tid + p * 512;
            int row = q >> 5, k4 = (q & 31) << 2;
            float4 v = rg[p];
            uint32_t off = row * ROWB + k4 * 2;
            uint32_t hi0 = pk_bf(v.x, v.y), hi1 = pk_bf(v.z, v.w);
            float l0 = v.x - bf_round(v.x), l1 = v.y - bf_round(v.y);
            float l2 = v.z - bf_round(v.z), l3 = v.w - bf_round(v.w);
            *reinterpret_cast<uint2*>(Ahi + off) = make_uint2(hi0, hi1);
            *reinterpret_cast<uint2*>(Alo + off) = make_uint2(pk_bf(l0, l1), pk_bf(l2, l3));
        }
    };

    float acc[2][4][4];

    auto mma_half = [&](int buf, int ks0) {
        const uint32_t AhiB = sb + SM_A + buf * (2 * IMS);
        const uint32_t AloB = AhiB + IMS;
        const uint32_t BhiB = sb, BloB = sb + IMS;
        #pragma unroll
        for (int ks = 0; ks < 4; ++ks) {
            const uint32_t ko = (uint32_t)(ks0 + ks) * 32;
            uint32_t bh[8], bl[8];
            #pragma unroll
            for (int np = 0; np < 2; ++np) {
                ldsm4(&bh[np * 4], BhiB + b_warp + np * 16 * ROWB + ko + b_lane);
                ldsm4(&bl[np * 4], BloB + b_warp + np * 16 * ROWB + ko + b_lane);
            }
            #pragma unroll
            for (int mt = 0; mt < 2; ++mt) {
                uint32_t ah[4], al[4];
                ldsm4(ah, AhiB + a_warp + mt * 16 * ROWB + ko + a_lane);
                ldsm4(al, AloB + a_warp + mt * 16 * ROWB + ko + a_lane);
                #pragma unroll
                for (int nt = 0; nt < 4; ++nt) {
                    const int bi = (nt >> 1) * 4 + (nt & 1) * 2;
                    mma_bf16(acc[mt][nt], ah, bh[bi], bh[bi + 1]);
                    mma_bf16(acc[mt][nt], ah, bl[bi], bl[bi + 1]);
                    mma_bf16(acc[mt][nt], al, bh[bi], bh[bi + 1]);
                }
            }
        }
    };

    // ---- prologue: stage tile 0 into buf 0 ----
    {
        float4 r0_[4], r1_[4];
        ldg_chunk(tstart, 0, r0_);
        ldg_chunk(tstart, 1, r1_);
        sts_chunk(0, 0, r0_);
        sts_chunk(0, 1, r1_);
    }
    __syncthreads();

    for (int i = 0;; ++i) {
        const int tile = tstart + i * tstep;
        const bool more = (i + 1 < nlocal);
        const int cur = i & 1, nxt = cur ^ 1;

        #pragma unroll
        for (int mt = 0; mt < 2; ++mt)
            #pragma unroll
            for (int nt = 0; nt < 4; ++nt)
                #pragma unroll
                for (int j = 0; j < 4; ++j) acc[mt][nt][j] = 0.f;

        float4 rg[4];
        if (more) ldg_chunk(tile + tstep, 0, rg);
        mma_half(cur, 0);
        if (more) { sts_chunk(nxt, 0, rg); ldg_chunk(tile + tstep, 1, rg); }
        mma_half(cur, 4);
        if (more) sts_chunk(nxt, 1, rg);

        // ---- epilogue ----
        float* hpB = g_hp + (size_t)tile * 16384;
        const int l2 = (l & 3) * 2;
        const float wdE0 = waS[16 + l2], wdE1 = waS[17 + l2];     // nt even (hd 0..7)
        const float wdO0 = waS[24 + l2], wdO1 = waS[25 + l2];     // nt odd (hd 8..15)
        const bool is_n0 = ((tile & (N_ - 1)) == 0);

        #pragma unroll
        for (int mt = 0; mt < 2; ++mt) {
            const int r0 = wr * 32 + mt * 16 + (l >> 2), r1 = r0 + 8;
            float p0[2] = {0, 0}, p1[2] = {0, 0};
            #pragma unroll
            for (int nt = 0; nt < 4; ++nt) {
                const int col = wc * 32 + nt * 8 + l2;
                const float bv0 = b1s[col], bv1 = b1s[col + 1];
                const float v00 = acc[mt][nt][0] + bv0, v01 = acc[mt][nt][1] + bv1;
                const float v10 = acc[mt][nt][2] + bv0, v11 = acc[mt][nt][3] + bv1;
                *reinterpret_cast<float2*>(&hpB[(size_t)r0 * 128 + col]) = make_float2(v00, v01);
                *reinterpret_cast<float2*>(&hpB[(size_t)r1 * 128 + col]) = make_float2(v10, v11);
                const float w0 = (nt & 1) ? wdO0 : wdE0;
                const float w1 = (nt & 1) ? wdO1 : wdE1;
                p0[nt >> 1] += v00 * w0 + v01 * w1;
                p1[nt >> 1] += v10 * w0 + v11 * w1;
            }
            #pragma unroll
            for (int h2 = 0; h2 < 2; ++h2) {
                p0[h2] += __shfl_xor_sync(~0u, p0[h2], 1);
                p0[h2] += __shfl_xor_sync(~0u, p0[h2], 2);
                p1[h2] += __shfl_xor_sync(~0u, p1[h2], 1);
                p1[h2] += __shfl_xor_sync(~0u, p1[h2], 2);
            }
            if ((l & 3) == 0) {
                *reinterpret_cast<float2*>(&g_sj[((size_t)tile * 128 + r0) * 8 + wc * 2]) =
                    make_float2(p0[0], p0[1]);
                *reinterpret_cast<float2*>(&g_sj[((size_t)tile * 128 + r1) * 8 + wc * 2]) =
                    make_float2(p1[0], p1[1]);
            }
            if (is_n0) {
                const float wsE0 = waS[l2], wsE1 = waS[l2 + 1];
                const float wsO0 = waS[8 + l2], wsO1 = waS[9 + l2];
                float q0[2] = {0, 0}, q1[2] = {0, 0};
                #pragma unroll
                for (int nt = 0; nt < 4; ++nt) {
                    const int col = wc * 32 + nt * 8 + l2;
                    const float bv0 = b1s[col], bv1 = b1s[col + 1];
                    const float w0 = (nt & 1) ? wsO0 : wsE0;
                    const float w1 = (nt & 1) ? wsO1 : wsE1;
                    q0[nt >> 1] += (acc[mt][nt][0] + bv0) * w0 + (acc[mt][nt][1] + bv1) * w1;
                    q1[nt >> 1] += (acc[mt][nt][2] + bv0) * w0 + (acc[mt][nt][3] + bv1) * w1;
                }
                #pragma unroll
                for (int h2 = 0; h2 < 2; ++h2) {
                    q0[h2] += __shfl_xor_sync(~0u, q0[h2], 1);
                    q0[h2] += __shfl_xor_sync(~0u, q0[h2], 2);
                    q1[h2] += __shfl_xor_sync(~0u, q1[h2], 1);
                    q1[h2] += __shfl_xor_sync(~0u, q1[h2], 2);
                }
                if ((l & 3) == 0) {
                    const int b = tile >> 9;
                    *reinterpret_cast<float2*>(&g_s0[(b * 128 + r0) * 8 + wc * 2]) =
                        make_float2(q0[0], q0[1]);
                    *reinterpret_cast<float2*>(&g_s0[(b * 128 + r1) * 8 + wc * 2]) =
                        make_float2(q1[0], q1[1]);
                }
            }
        }
        __syncthreads();
        if (!more) break;
    }
}

// ===================== k_softagg: softmax + aggregation + projection =====================
__global__ __launch_bounds__(256) void k_softagg(
    const float* __restrict__ adj, const float* __restrict__ mask,
    const float* __restrict__ ba, const float* __restrict__ W2,
    const float* __restrict__ b2, float* __restrict__ out)
{
    __shared__ float aS[512];
    __shared__ float mS[512];
    __shared__ float sS[512 * 9];
    __shared__ float atS[8 * 512];
    __shared__ float pacc[256];
    __shared__ float cat[256];
    const int bt = blockIdx.x;
    const int b = bt >> 7, t = bt & 127;
    const int tid = threadIdx.x;

    // ---- phase 1: attn into smem ----
    for (int q = tid; q < 512; q += 256) {
        float av = adj[(size_t)bt * 512 + q];
        float mv = mask[((size_t)b * 512 + q) * 128 + t];
        av = (av == 0.f) ? 1e9f : av;
        av = (mv > 0.f) ? (1.f / av) : av;
        aS[q] = av;
        mS[q] = mv;
    }
    for (int q = tid; q < 4096; q += 256) {
        int n = q >> 3, hv = q & 7;
        sS[n * 9 + hv] = g_sj[(size_t)b * 524288 + (size_t)n * 1024 + t * 8 + hv];
    }
    __syncthreads();

    {
        const int hh = tid >> 5, lane = tid & 31;
        const float s0v = g_s0[bt * 8 + hh] + ba[0];
        float v[16];
        float mx = -3.4e38f;
        #pragma unroll
        for (int u = 0; u < 16; ++u) {
            int nn = lane + 32 * u;
            float s = sS[nn * 9 + hh] + s0v;
            if (mS[nn] == 0.f) s = -1e9f;
            v[u] = s;
            mx = fmaxf(mx, s);
        }
        #pragma unroll
        for (int o = 16; o; o >>= 1) mx = fmaxf(mx, __shfl_xor_sync(~0u, mx, o));
        float sum = 0.f;
        #pragma unroll
        for (int u = 0; u < 16; ++u) { float e = __expf(v[u] - mx); v[u] = e; sum += e; }
        #pragma unroll
        for (int o = 16; o; o >>= 1) sum += __shfl_xor_sync(~0u, sum, o);
        const float inv = 1.f / sum;
        #pragma unroll
        for (int u = 0; u < 16; ++u) {
            int nn = lane + 32 * u;
            atS[hh * 512 + nn] = v[u] * inv * aS[nn];
        }
    }
    __syncthreads();

    // ---- phase 2: agg (two n-halves per feature for 2x MLP) ----
    const int e = tid & 127, half = tid >> 7;
    const float* hb = g_hp + ((size_t)b * 65536 + t) * 128 + e;
    const float* arow = atS + (e >> 4) * 512;

    float a0 = 0.f, a1 = 0.f, a2 = 0.f, a3 = 0.f;
    #pragma unroll 2
    for (int n = half; n < 512; n += 8) {
        a0 = fmaf(arow[n],     hb[(size_t)n * 16384],       a0);
        a1 = fmaf(arow[n + 2], hb[(size_t)(n + 2) * 16384], a1);
        a2 = fmaf(arow[n + 4], hb[(size_t)(n + 4) * 16384], a2);
        a3 = fmaf(arow[n + 6], hb[(size_t)(n + 6) * 16384], a3);
    }
    pacc[tid] = (a0 + a1) + (a2 + a3);
    if (half == 0) cat[128 + e] = hb[0];   // target_h (n == 0)
    __syncthreads();
    if (tid < 128) cat[tid] = pacc[tid] + pacc[128 + tid];
    __syncthreads();

    // ---- phase 3: final projection ----
    if (tid < 128) {
        float o = b2[e];
        #pragma unroll 8
        for (int k2 = 0; k2 < 256; ++k2) o = fmaf(cat[k2], W2[k2 * 128 + e], o);
        out[(size_t)bt * 128 + e] = o;
    }
}

// ===================== launch =====================
extern "C" void kernel_launch(void* const* d_in, const int* in_sizes, int n_in,
                              void* d_out, int out_size)
{
    const float* h    = (const float*)d_in[0];
    const float* adj  = (const float*)d_in[1];
    const float* mask = (const float*)d_in[2];
    const float* W1   = (const float*)d_in[3];
    const float* b1   = (const float*)d_in[4];
    const float* Wa   = (const float*)d_in[5];
    const float* ba   = (const float*)d_in[6];
    const float* W2   = (const float*)d_in[7];
    const float* b2   = (const float*)d_in[8];
    float* out = (float*)d_out;

    cudaFuncSetAttribute(k_gemm, cudaFuncAttributeMaxDynamicSharedMemorySize,
                         SMEM_TOTAL);

    k_prep<<<64, 256>>>(W1);
    k_gemm<<<GRID_GEMM, 512, SMEM_TOTAL>>>(h, b1, Wa);
    k_softagg<<<B_ * T_, 256>>>(adj, mask, ba, W2, b2, out);
}

// round 8
// speedup vs baseline: 1.0972x; 1.0972x over previous
#include <cuda_runtime.h>
#include <cuda_bf16.h>
#include <cstdint>

#define B_ 8
#define N_ 512
#define T_ 128
#define H_ 8

#define NTILES 4096        // tile = 128 rows (all t for one (b,n)) x 128 cols
#define GRID_GEMM 152
#define ROWB 272           // padded row stride in bytes -> conflict-free ldmatrix
#define IMS 34816          // one 128x128 bf16 image = 128*272 bytes

// -------- scratch (device globals: allocation-free) --------
__device__ float g_hp[(size_t)B_ * N_ * T_ * 128];      // [b][n][t][e]
__device__ float g_sj[(size_t)B_ * N_ * T_ * H_];       // [b][n][t][h]
__device__ float g_s0[B_ * T_ * H_];                    // [b][t][h]
__device__ float g_attn[(size_t)B_ * T_ * H_ * N_];     // [b][t][h][n]

// ---------------- helpers ----------------
__device__ __forceinline__ uint32_t smem_u32(const void* p) {
    uint32_t a;
    asm("{ .reg .u64 t; cvta.to.shared.u64 t, %1; cvt.u32.u64 %0, t; }" : "=r"(a) : "l"(p));
    return a;
}
__device__ __forceinline__ void ldsm4(uint32_t* r, uint32_t addr) {
    asm volatile("ldmatrix.sync.aligned.m8n8.x4.shared.b16 {%0,%1,%2,%3}, [%4];"
                 : "=r"(r[0]), "=r"(r[1]), "=r"(r[2]), "=r"(r[3]) : "r"(addr));
}
__device__ __forceinline__ void mma_bf16(float* c, const uint32_t* a,
                                         uint32_t b0, uint32_t b1) {
    asm volatile(
        "mma.sync.aligned.m16n8k16.row.col.f32.bf16.bf16.f32 "
        "{%0,%1,%2,%3}, {%4,%5,%6,%7}, {%8,%9}, {%0,%1,%2,%3};"
        : "+f"(c[0]), "+f"(c[1]), "+f"(c[2]), "+f"(c[3])
        : "r"(a[0]), "r"(a[1]), "r"(a[2]), "r"(a[3]), "r"(b0), "r"(b1));
}
__device__ __forceinline__ uint32_t pk_bf(float a, float b) {  // lo-half=a, hi-half=b
    uint32_t r;
    asm("cvt.rn.bf16x2.f32 %0, %1, %2;" : "=r"(r) : "f"(b), "f"(a));
    return r;
}
__device__ __forceinline__ float bf_round(float x) {
    return __bfloat162float(__float2bfloat16(x));
}

// ===================== k_gemm: persistent mma.sync split-bf16 GEMM =====================
// smem: Whi@0, Wlo@IMS, A[buf][hi/lo]@69632+buf*2*IMS(+IMS), b1@208896, Wa@209408
#define SM_A     69632
#define SM_B1    208896
#define SM_WA    209408
#define SMEM_TOTAL 209536

__global__ __launch_bounds__(256, 1) void k_gemm(
    const float* __restrict__ h, const float* __restrict__ W1,
    const float* __restrict__ b1, const float* __restrict__ Wa)
{
    extern __shared__ char smem[];
    const uint32_t sb = smem_u32(smem);
    const int tid = threadIdx.x, wid = tid >> 5, l = tid & 31;
    const int wr = wid >> 1, wc = wid & 1;     // warp grid 4x2 (rows x cols)

    // ---- one-time: build W^T hi/lo images in smem directly from W1 ----
    {
        #pragma unroll
        for (int p = 0; p < 16; ++p) {
            int q = tid + p * 256;              // 4096 float4 = 16384 elems
            float4 w4 = reinterpret_cast<const float4*>(W1)[q];
            int k = q >> 5, e4 = (q & 31) << 2; // W1[k][e4..e4+3]
            #pragma unroll
            for (int u = 0; u < 4; ++u) {
                float w = (u == 0) ? w4.x : (u == 1) ? w4.y : (u == 2) ? w4.z : w4.w;
                uint32_t off = (uint32_t)(e4 + u) * ROWB + (uint32_t)k * 2;
                *reinterpret_cast<__nv_bfloat16*>(smem + off) = __float2bfloat16(w);
                *reinterpret_cast<__nv_bfloat16*>(smem + IMS + off) =
                    __float2bfloat16(w - bf_round(w));
            }
        }
    }
    if (tid < 128) ((float*)(smem + SM_B1))[tid] = b1[tid];
    if (tid < 32)  ((float*)(smem + SM_WA))[tid] = Wa[tid];

    const float* b1s = (const float*)(smem + SM_B1);
    const float* waS = (const float*)(smem + SM_WA);

    // per-lane ldmatrix offsets
    const uint32_t a_lane = (uint32_t)((l & 15) * ROWB + (l >> 4) * 16);
    const uint32_t b_lane = (uint32_t)(((l >> 4) * 8 + (l & 7)) * ROWB + ((l >> 3) & 1) * 16);
    const uint32_t a_warp = (uint32_t)(wr * 32) * ROWB;
    const uint32_t b_warp = (uint32_t)(wc * 64) * ROWB;

    const int tstart = blockIdx.x, tstep = gridDim.x;
    const int nlocal = (NTILES - tstart + tstep - 1) / tstep;

    auto ldg_chunk = [&](int tile, int c, float4* rg) {
        const float4* hg = reinterpret_cast<const float4*>(h + (size_t)tile * 16384);
        #pragma unroll
        for (int p = 0; p < 8; ++p) rg[p] = hg[c * 2048 + tid + p * 256];
    };
    auto sts_chunk = [&](int buf, int c, const float4* rg) {
        char* Ahi = smem + SM_A + buf * (2 * IMS);
        char* Alo = Ahi + IMS;
        #pragma unroll
        for (int p = 0; p < 8; ++p) {
            int q = c * 2048 + tid + p * 256;
            int row = q >> 5, k4 = (q & 31) << 2;
            float4 v = rg[p];
            uint32_t off = row * ROWB + k4 * 2;
            uint32_t hi0 = pk_bf(v.x, v.y), hi1 = pk_bf(v.z, v.w);
            float l0 = v.x - bf_round(v.x), l1 = v.y - bf_round(v.y);
            float l2 = v.z - bf_round(v.z), l3 = v.w - bf_round(v.w);
            *reinterpret_cast<uint2*>(Ahi + off) = make_uint2(hi0, hi1);
            *reinterpret_cast<uint2*>(Alo + off) = make_uint2(pk_bf(l0, l1), pk_bf(l2, l3));
        }
    };

    float acc[2][8][4];

    auto mma_half = [&](int buf, int ks0) {
        const uint32_t AhiB = sb + SM_A + buf * (2 * IMS);
        const uint32_t AloB = AhiB + IMS;
        const uint32_t BhiB = sb, BloB = sb + IMS;
        #pragma unroll
        for (int ks = 0; ks < 4; ++ks) {
            const uint32_t ko = (uint32_t)(ks0 + ks) * 32;
            uint32_t bh[16], bl[16];
            #pragma unroll
            for (int np = 0; np < 4; ++np) {
                ldsm4(&bh[np * 4], BhiB + b_warp + np * 16 * ROWB + ko + b_lane);
                ldsm4(&bl[np * 4], BloB + b_warp + np * 16 * ROWB + ko + b_lane);
            }
            #pragma unroll
            for (int mt = 0; mt < 2; ++mt) {
                uint32_t ah[4], al[4];
                ldsm4(ah, AhiB + a_warp + mt * 16 * ROWB + ko + a_lane);
                ldsm4(al, AloB + a_warp + mt * 16 * ROWB + ko + a_lane);
                #pragma unroll
                for (int nt = 0; nt < 8; ++nt) {
                    const int bi = (nt >> 1) * 4 + (nt & 1) * 2;
                    mma_bf16(acc[mt][nt], ah, bh[bi], bh[bi + 1]);
                    mma_bf16(acc[mt][nt], ah, bl[bi], bl[bi + 1]);
                    mma_bf16(acc[mt][nt], al, bh[bi], bh[bi + 1]);
                }
            }
        }
    };

    // ---- prologue: stage tile 0 into buf 0 ----
    {
        float4 r0_[8], r1_[8];
        ldg_chunk(tstart, 0, r0_);
        ldg_chunk(tstart, 1, r1_);
        sts_chunk(0, 0, r0_);
        sts_chunk(0, 1, r1_);
    }
    __syncthreads();

    for (int i = 0;; ++i) {
        const int tile = tstart + i * tstep;
        const bool more = (i + 1 < nlocal);
        const int cur = i & 1, nxt = cur ^ 1;

        #pragma unroll
        for (int mt = 0; mt < 2; ++mt)
            #pragma unroll
            for (int nt = 0; nt < 8; ++nt)
                #pragma unroll
                for (int j = 0; j < 4; ++j) acc[mt][nt][j] = 0.f;

        float4 rg[8];
        if (more) ldg_chunk(tile + tstep, 0, rg);
        mma_half(cur, 0);
        if (more) { sts_chunk(nxt, 0, rg); ldg_chunk(tile + tstep, 1, rg); }
        mma_half(cur, 4);
        if (more) sts_chunk(nxt, 1, rg);

        // ---- epilogue ----
        float* hpB = g_hp + (size_t)tile * 16384;
        const float wd0e = waS[16 + (l & 3) * 2], wd1e = waS[17 + (l & 3) * 2];
        const float wd0o = waS[24 + (l & 3) * 2], wd1o = waS[25 + (l & 3) * 2];
        const bool is_n0 = ((tile & (N_ - 1)) == 0);

        #pragma unroll
        for (int mt = 0; mt < 2; ++mt) {
            const int r0 = wr * 32 + mt * 16 + (l >> 2), r1 = r0 + 8;
            float p0[4] = {0, 0, 0, 0}, p1[4] = {0, 0, 0, 0};
            #pragma unroll
            for (int nt = 0; nt < 8; ++nt) {
                const int col = wc * 64 + nt * 8 + (l & 3) * 2;
                const float bv0 = b1s[col], bv1 = b1s[col + 1];
                const float v00 = acc[mt][nt][0] + bv0, v01 = acc[mt][nt][1] + bv1;
                const float v10 = acc[mt][nt][2] + bv0, v11 = acc[mt][nt][3] + bv1;
                *reinterpret_cast<float2*>(&hpB[(size_t)r0 * 128 + col]) = make_float2(v00, v01);
                *reinterpret_cast<float2*>(&hpB[(size_t)r1 * 128 + col]) = make_float2(v10, v11);
                const float w0 = (nt & 1) ? wd0o : wd0e;
                const float w1 = (nt & 1) ? wd1o : wd1e;
                p0[nt >> 1] += v00 * w0 + v01 * w1;
                p1[nt >> 1] += v10 * w0 + v11 * w1;
            }
            #pragma unroll
            for (int h4 = 0; h4 < 4; ++h4) {
                p0[h4] += __shfl_xor_sync(~0u, p0[h4], 1);
                p0[h4] += __shfl_xor_sync(~0u, p0[h4], 2);
                p1[h4] += __shfl_xor_sync(~0u, p1[h4], 1);
                p1[h4] += __shfl_xor_sync(~0u, p1[h4], 2);
            }
            if ((l & 3) == 0) {
                *reinterpret_cast<float4*>(&g_sj[((size_t)tile * 128 + r0) * 8 + wc * 4]) =
                    make_float4(p0[0], p0[1], p0[2], p0[3]);
                *reinterpret_cast<float4*>(&g_sj[((size_t)tile * 128 + r1) * 8 + wc * 4]) =
                    make_float4(p1[0], p1[1], p1[2], p1[3]);
            }
            if (is_n0) {
                const float ws0e = waS[(l & 3) * 2], ws1e = waS[1 + (l & 3) * 2];
                const float ws0o = waS[8 + (l & 3) * 2], ws1o = waS[9 + (l & 3) * 2];
                float q0[4] = {0, 0, 0, 0}, q1[4] = {0, 0, 0, 0};
                #pragma unroll
                for (int nt = 0; nt < 8; ++nt) {
                    const int col = wc * 64 + nt * 8 + (l & 3) * 2;
                    const float bv0 = b1s[col], bv1 = b1s[col + 1];
                    const float w0 = (nt & 1) ? ws0o : ws0e;
                    const float w1 = (nt & 1) ? ws1o : ws1e;
                    q0[nt >> 1] += (acc[mt][nt][0] + bv0) * w0 + (acc[mt][nt][1] + bv1) * w1;
                    q1[nt >> 1] += (acc[mt][nt][2] + bv0) * w0 + (acc[mt][nt][3] + bv1) * w1;
                }
                #pragma unroll
                for (int h4 = 0; h4 < 4; ++h4) {
                    q0[h4] += __shfl_xor_sync(~0u, q0[h4], 1);
                    q0[h4] += __shfl_xor_sync(~0u, q0[h4], 2);
                    q1[h4] += __shfl_xor_sync(~0u, q1[h4], 1);
                    q1[h4] += __shfl_xor_sync(~0u, q1[h4], 2);
                }
                if ((l & 3) == 0) {
                    const int b = tile >> 9;
                    *reinterpret_cast<float4*>(&g_s0[(b * 128 + r0) * 8 + wc * 4]) =
                        make_float4(q0[0], q0[1], q0[2], q0[3]);
                    *reinterpret_cast<float4*>(&g_s0[(b * 128 + r1) * 8 + wc * 4]) =
                        make_float4(q1[0], q1[1], q1[2], q1[3]);
                }
            }
        }
        __syncthreads();
        if (!more) break;
    }
}

// ===================== k_soft: masked softmax * adj-scale =====================
__global__ __launch_bounds__(256) void k_soft(
    const float* __restrict__ adj, const float* __restrict__ mask,
    const float* __restrict__ ba)
{
    __shared__ float aS[512];
    __shared__ float mS[512];
    __shared__ float sS[512 * 9];
    const int bt = blockIdx.x;
    const int b = bt >> 7, t = bt & 127;
    const int tid = threadIdx.x;

    for (int q = tid; q < 512; q += 256) {
        float av = adj[(size_t)bt * 512 + q];
        float mv = mask[((size_t)b * 512 + q) * 128 + t];
        av = (av == 0.f) ? 1e9f : av;
        av = (mv > 0.f) ? (1.f / av) : av;
        aS[q] = av;
        mS[q] = mv;
    }
    for (int q = tid; q < 4096; q += 256) {
        int n = q >> 3, hv = q & 7;
        sS[n * 9 + hv] = g_sj[(size_t)b * 524288 + (size_t)n * 1024 + t * 8 + hv];
    }
    __syncthreads();

    const int hh = tid >> 5, lane = tid & 31;
    const float s0v = g_s0[bt * 8 + hh] + ba[0];

    float v[16];
    float mx = -3.4e38f;
    #pragma unroll
    for (int u = 0; u < 16; ++u) {
        int nn = lane + 32 * u;
        float s = sS[nn * 9 + hh] + s0v;
        if (mS[nn] == 0.f) s = -1e9f;
        v[u] = s;
        mx = fmaxf(mx, s);
    }
    #pragma unroll
    for (int o = 16; o; o >>= 1) mx = fmaxf(mx, __shfl_xor_sync(~0u, mx, o));
    float sum = 0.f;
    #pragma unroll
    for (int u = 0; u < 16; ++u) { float e = __expf(v[u] - mx); v[u] = e; sum += e; }
    #pragma unroll
    for (int o = 16; o; o >>= 1) sum += __shfl_xor_sync(~0u, sum, o);
    const float inv = 1.f / sum;

    float* ar = g_attn + ((size_t)bt * 8 + hh) * 512;
    #pragma unroll
    for (int u = 0; u < 16; ++u) {
        int nn = lane + 32 * u;
        ar[nn] = v[u] * inv * aS[nn];
    }
}

// ===================== k_agg: aggregation + final projection =====================
// 256 threads: feature e = tid&127, n-half = tid>>7 (doubles per-thread MLP).
__global__ __launch_bounds__(256) void k_agg(
    const float* __restrict__ W2, const float* __restrict__ b2,
    float* __restrict__ out)
{
    __shared__ float atS[8 * 512];
    __shared__ float pacc[256];
    __shared__ float cat[256];
    const int bt = blockIdx.x;
    const int b = bt >> 7, t = bt & 127;
    const int tid = threadIdx.x;
    const int e = tid & 127, half = tid >> 7;

    const float* ab = g_attn + (size_t)bt * 4096;
    for (int q = tid; q < 4096; q += 256) atS[q] = ab[q];
    __syncthreads();

    const float* hb = g_hp + ((size_t)b * 65536 + t) * 128 + e;
    const float* arow = atS + (e >> 4) * 512;

    float a0 = 0.f, a1 = 0.f, a2 = 0.f, a3 = 0.f;
    #pragma unroll 2
    for (int n = half; n < 512; n += 8) {
        a0 = fmaf(arow[n],     hb[(size_t)n * 16384],       a0);
        a1 = fmaf(arow[n + 2], hb[(size_t)(n + 2) * 16384], a1);
        a2 = fmaf(arow[n + 4], hb[(size_t)(n + 4) * 16384], a2);
        a3 = fmaf(arow[n + 6], hb[(size_t)(n + 6) * 16384], a3);
    }
    pacc[tid] = (a0 + a1) + (a2 + a3);
    if (half == 0) cat[128 + e] = hb[0];   // target_h (n == 0)
    __syncthreads();
    if (tid < 128) cat[tid] = pacc[tid] + pacc[128 + tid];
    __syncthreads();

    if (tid < 128) {
        float o = b2[e];
        #pragma unroll 8
        for (int k2 = 0; k2 < 256; ++k2) o = fmaf(cat[k2], W2[k2 * 128 + e], o);
        out[(size_t)bt * 128 + e] = o;
    }
}

// ===================== launch =====================
extern "C" void kernel_launch(void* const* d_in, const int* in_sizes, int n_in,
                              void* d_out, int out_size)
{
    const float* h    = (const float*)d_in[0];
    const float* adj  = (const float*)d_in[1];
    const float* mask = (const float*)d_in[2];
    const float* W1   = (const float*)d_in[3];
    const float* b1   = (const float*)d_in[4];
    const float* Wa   = (const float*)d_in[5];
    const float* ba   = (const float*)d_in[6];
    const float* W2   = (const float*)d_in[7];
    const float* b2   = (const float*)d_in[8];
    float* out = (float*)d_out;

    cudaFuncSetAttribute(k_gemm, cudaFuncAttributeMaxDynamicSharedMemorySize,
                         SMEM_TOTAL);

    k_gemm<<<GRID_GEMM, 256, SMEM_TOTAL>>>(h, W1, b1, Wa);
    k_soft<<<B_ * T_, 256>>>(adj, mask, ba);
    k_agg<<<B_ * T_, 256>>>(W2, b2, out);
}

// round 10
// speedup vs baseline: 1.2640x; 1.1520x over previous
#include <cuda_runtime.h>
#include <cuda_fp16.h>
#include <cstdint>

#define B_ 8
#define N_ 512
#define T_ 128
#define H_ 8

#define NTILES 4096        // tile = 128 rows (all t for one (b,n)) x 128 cols
#define GRID_GEMM 152
#define ROWB 272           // padded row stride in bytes -> conflict-free ldmatrix
#define IMS 34816          // one 128x128 fp16 image = 128*272 bytes

// -------- scratch (device globals: allocation-free) --------
__device__ float g_hp[(size_t)B_ * N_ * T_ * 128];      // [b][n][t][e]
__device__ float g_sj[(size_t)B_ * N_ * T_ * H_];       // [b][n][t][h]
__device__ float g_s0[B_ * T_ * H_];                    // [b][t][h]
__device__ float g_attn[(size_t)B_ * T_ * H_ * N_];     // [b][t][h][n]

// ---------------- helpers ----------------
__device__ __forceinline__ uint32_t smem_u32(const void* p) {
    uint32_t a;
    asm("{ .reg .u64 t; cvta.to.shared.u64 t, %1; cvt.u32.u64 %0, t; }" : "=r"(a) : "l"(p));
    return a;
}
__device__ __forceinline__ void ldsm4(uint32_t* r, uint32_t addr) {
    asm volatile("ldmatrix.sync.aligned.m8n8.x4.shared.b16 {%0,%1,%2,%3}, [%4];"
                 : "=r"(r[0]), "=r"(r[1]), "=r"(r[2]), "=r"(r[3]) : "r"(addr));
}
__device__ __forceinline__ void mma_f16(float* c, const uint32_t* a,
                                        uint32_t b0, uint32_t b1) {
    asm volatile(
        "mma.sync.aligned.m16n8k16.row.col.f32.f16.f16.f32 "
        "{%0,%1,%2,%3}, {%4,%5,%6,%7}, {%8,%9}, {%0,%1,%2,%3};"
        : "+f"(c[0]), "+f"(c[1]), "+f"(c[2]), "+f"(c[3])
        : "r"(a[0]), "r"(a[1]), "r"(a[2]), "r"(a[3]), "r"(b0), "r"(b1));
}
__device__ __forceinline__ uint32_t pk_h(float a, float b) {  // lo-half=a, hi-half=b
    uint32_t r;
    asm("cvt.rn.f16x2.f32 %0, %1, %2;" : "=r"(r) : "f"(b), "f"(a));
    return r;
}
__device__ __forceinline__ float h_round(float x) {
    return __half2float(__float2half(x));
}

// ===================== k_gemm: persistent mma.sync 2-pass fp16 GEMM =====================
// smem: Whi@0, Wlo@IMS, A[buf]@2*IMS + buf*IMS, b1@4*IMS, Wa@4*IMS+512
#define SM_A     (2 * IMS)
#define SM_B1    (4 * IMS)
#define SM_WA    (4 * IMS + 512)
#define SMEM_TOTAL (4 * IMS + 640)

__global__ __launch_bounds__(256, 1) void k_gemm(
    const float* __restrict__ h, const float* __restrict__ W1,
    const float* __restrict__ b1, const float* __restrict__ Wa)
{
    extern __shared__ char smem[];
    const uint32_t sb = smem_u32(smem);
    const int tid = threadIdx.x, wid = tid >> 5, l = tid & 31;
    const int wr = wid >> 1, wc = wid & 1;     // warp grid 4x2 (rows x cols)

    // ---- one-time: build W^T hi/lo fp16 images in smem directly from W1 ----
    {
        #pragma unroll
        for (int p = 0; p < 16; ++p) {
            int q = tid + p * 256;              // 4096 float4 = 16384 elems
            float4 w4 = reinterpret_cast<const float4*>(W1)[q];
            int k = q >> 5, e4 = (q & 31) << 2; // W1[k][e4..e4+3]
            #pragma unroll
            for (int u = 0; u < 4; ++u) {
                float w = (u == 0) ? w4.x : (u == 1) ? w4.y : (u == 2) ? w4.z : w4.w;
                uint32_t off = (uint32_t)(e4 + u) * ROWB + (uint32_t)k * 2;
                *reinterpret_cast<__half*>(smem + off) = __float2half(w);
                *reinterpret_cast<__half*>(smem + IMS + off) =
                    __float2half(w - h_round(w));
            }
        }
    }
    if (tid < 128) ((float*)(smem + SM_B1))[tid] = b1[tid];
    if (tid < 32)  ((float*)(smem + SM_WA))[tid] = Wa[tid];

    const float* b1s = (const float*)(smem + SM_B1);
    const float* waS = (const float*)(smem + SM_WA);

    // per-lane ldmatrix offsets
    const uint32_t a_lane = (uint32_t)((l & 15) * ROWB + (l >> 4) * 16);
    const uint32_t b_lane = (uint32_t)(((l >> 4) * 8 + (l & 7)) * ROWB + ((l >> 3) & 1) * 16);
    const uint32_t a_warp = (uint32_t)(wr * 32) * ROWB;
    const uint32_t b_warp = (uint32_t)(wc * 64) * ROWB;

    const int tstart = blockIdx.x, tstep = gridDim.x;
    const int nlocal = (NTILES - tstart + tstep - 1) / tstep;

    auto ldg_chunk = [&](int tile, int c, float4* rg) {
        const float4* hg = reinterpret_cast<const float4*>(h + (size_t)tile * 16384);
        #pragma unroll
        for (int p = 0; p < 8; ++p) rg[p] = hg[c * 2048 + tid + p * 256];
    };
    auto sts_chunk = [&](int buf, int c, const float4* rg) {
        char* Ah = smem + SM_A + buf * IMS;
        #pragma unroll
        for (int p = 0; p < 8; ++p) {
            int q = c * 2048 + tid + p * 256;
            int row = q >> 5, k4 = (q & 31) << 2;
            float4 v = rg[p];
            *reinterpret_cast<uint2*>(Ah + row * ROWB + k4 * 2) =
                make_uint2(pk_h(v.x, v.y), pk_h(v.z, v.w));
        }
    };

    float acc[2][8][4];

    auto mma_half = [&](int buf, int ks0) {
        const uint32_t AB = sb + SM_A + buf * IMS;
        const uint32_t BhiB = sb, BloB = sb + IMS;
        #pragma unroll
        for (int ks = 0; ks < 4; ++ks) {
            const uint32_t ko = (uint32_t)(ks0 + ks) * 32;
            uint32_t bh[16], bl[16];
            #pragma unroll
            for (int np = 0; np < 4; ++np) {
                ldsm4(&bh[np * 4], BhiB + b_warp + np * 16 * ROWB + ko + b_lane);
                ldsm4(&bl[np * 4], BloB + b_warp + np * 16 * ROWB + ko + b_lane);
            }
            #pragma unroll
            for (int mt = 0; mt < 2; ++mt) {
                uint32_t ah[4];
                ldsm4(ah, AB + a_warp + mt * 16 * ROWB + ko + a_lane);
                #pragma unroll
                for (int nt = 0; nt < 8; ++nt) {
                    const int bi = (nt >> 1) * 4 + (nt & 1) * 2;
                    mma_f16(acc[mt][nt], ah, bh[bi], bh[bi + 1]);
                    mma_f16(acc[mt][nt], ah, bl[bi], bl[bi + 1]);
                }
            }
        }
    };

    // ---- prologue: stage tile 0 into buf 0 ----
    {
        float4 r0_[8], r1_[8];
        ldg_chunk(tstart, 0, r0_);
        ldg_chunk(tstart, 1, r1_);
        sts_chunk(0, 0, r0_);
        sts_chunk(0, 1, r1_);
    }
    __syncthreads();

    for (int i = 0;; ++i) {
        const int tile = tstart + i * tstep;
        const bool more = (i + 1 < nlocal);
        const int cur = i & 1, nxt = cur ^ 1;

        #pragma unroll
        for (int mt = 0; mt < 2; ++mt)
            #pragma unroll
            for (int nt = 0; nt < 8; ++nt)
                #pragma unroll
                for (int j = 0; j < 4; ++j) acc[mt][nt][j] = 0.f;

        float4 rg[8];
        if (more) ldg_chunk(tile + tstep, 0, rg);
        mma_half(cur, 0);
        if (more) { sts_chunk(nxt, 0, rg); ldg_chunk(tile + tstep, 1, rg); }
        mma_half(cur, 4);
        if (more) sts_chunk(nxt, 1, rg);

        // ---- epilogue ----
        float* hpB = g_hp + (size_t)tile * 16384;
        const float wd0e = waS[16 + (l & 3) * 2], wd1e = waS[17 + (l & 3) * 2];
        const float wd0o = waS[24 + (l & 3) * 2], wd1o = waS[25 + (l & 3) * 2];
        const bool is_n0 = ((tile & (N_ - 1)) == 0);

        #pragma unroll
        for (int mt = 0; mt < 2; ++mt) {
            const int r0 = wr * 32 + mt * 16 + (l >> 2), r1 = r0 + 8;
            float p0[4] = {0, 0, 0, 0}, p1[4] = {0, 0, 0, 0};
            #pragma unroll
            for (int nt = 0; nt < 8; ++nt) {
                const int col = wc * 64 + nt * 8 + (l & 3) * 2;
                const float bv0 = b1s[col], bv1 = b1s[col + 1];
                const float v00 = acc[mt][nt][0] + bv0, v01 = acc[mt][nt][1] + bv1;
                const float v10 = acc[mt][nt][2] + bv0, v11 = acc[mt][nt][3] + bv1;
                *reinterpret_cast<float2*>(&hpB[(size_t)r0 * 128 + col]) = make_float2(v00, v01);
                *reinterpret_cast<float2*>(&hpB[(size_t)r1 * 128 + col]) = make_float2(v10, v11);
                const float w0 = (nt & 1) ? wd0o : wd0e;
                const float w1 = (nt & 1) ? wd1o : wd1e;
                p0[nt >> 1] += v00 * w0 + v01 * w1;
                p1[nt >> 1] += v10 * w0 + v11 * w1;
            }
            #pragma unroll
            for (int h4 = 0; h4 < 4; ++h4) {
                p0[h4] += __shfl_xor_sync(~0u, p0[h4], 1);
                p0[h4] += __shfl_xor_sync(~0u, p0[h4], 2);
                p1[h4] += __shfl_xor_sync(~0u, p1[h4], 1);
                p1[h4] += __shfl_xor_sync(~0u, p1[h4], 2);
            }
            if ((l & 3) == 0) {
                *reinterpret_cast<float4*>(&g_sj[((size_t)tile * 128 + r0) * 8 + wc * 4]) =
                    make_float4(p0[0], p0[1], p0[2], p0[3]);
                *reinterpret_cast<float4*>(&g_sj[((size_t)tile * 128 + r1) * 8 + wc * 4]) =
                    make_float4(p1[0], p1[1], p1[2], p1[3]);
            }
            if (is_n0) {
                const float ws0e = waS[(l & 3) * 2], ws1e = waS[1 + (l & 3) * 2];
                const float ws0o = waS[8 + (l & 3) * 2], ws1o = waS[9 + (l & 3) * 2];
                float q0[4] = {0, 0, 0, 0}, q1[4] = {0, 0, 0, 0};
                #pragma unroll
                for (int nt = 0; nt < 8; ++nt) {
                    const int col = wc * 64 + nt * 8 + (l & 3) * 2;
                    const float bv0 = b1s[col], bv1 = b1s[col + 1];
                    const float w0 = (nt & 1) ? ws0o : ws0e;
                    const float w1 = (nt & 1) ? ws1o : ws1e;
                    q0[nt >> 1] += (acc[mt][nt][0] + bv0) * w0 + (acc[mt][nt][1] + bv1) * w1;
                    q1[nt >> 1] += (acc[mt][nt][2] + bv0) * w0 + (acc[mt][nt][3] + bv1) * w1;
                }
                #pragma unroll
                for (int h4 = 0; h4 < 4; ++h4) {
                    q0[h4] += __shfl_xor_sync(~0u, q0[h4], 1);
                    q0[h4] += __shfl_xor_sync(~0u, q0[h4], 2);
                    q1[h4] += __shfl_xor_sync(~0u, q1[h4], 1);
                    q1[h4] += __shfl_xor_sync(~0u, q1[h4], 2);
                }
                if ((l & 3) == 0) {
                    const int b = tile >> 9;
                    *reinterpret_cast<float4*>(&g_s0[(b * 128 + r0) * 8 + wc * 4]) =
                        make_float4(q0[0], q0[1], q0[2], q0[3]);
                    *reinterpret_cast<float4*>(&g_s0[(b * 128 + r1) * 8 + wc * 4]) =
                        make_float4(q1[0], q1[1], q1[2], q1[3]);
                }
            }
        }
        __syncthreads();
        if (!more) break;
    }
}

// ===================== k_soft: masked softmax * adj-scale =====================
__global__ __launch_bounds__(256) void k_soft(
    const float* __restrict__ adj, const float* __restrict__ mask,
    const float* __restrict__ ba)
{
    __shared__ float aS[512];
    __shared__ float mS[512];
    __shared__ float sS[512 * 9];
    const int bt = blockIdx.x;
    const int b = bt >> 7, t = bt & 127;
    const int tid = threadIdx.x;

    for (int q = tid; q < 512; q += 256) {
        float av = adj[(size_t)bt * 512 + q];
        float mv = mask[((size_t)b * 512 + q) * 128 + t];
        av = (av == 0.f) ? 1e9f : av;
        av = (mv > 0.f) ? (1.f / av) : av;
        aS[q] = av;
        mS[q] = mv;
    }
    for (int q = tid; q < 4096; q += 256) {
        int n = q >> 3, hv = q & 7;
        sS[n * 9 + hv] = g_sj[(size_t)b * 524288 + (size_t)n * 1024 + t * 8 + hv];
    }
    __syncthreads();

    const int hh = tid >> 5, lane = tid & 31;
    const float s0v = g_s0[bt * 8 + hh] + ba[0];

    float v[16];
    float mx = -3.4e38f;
    #pragma unroll
    for (int u = 0; u < 16; ++u) {
        int nn = lane + 32 * u;
        float s = sS[nn * 9 + hh] + s0v;
        if (mS[nn] == 0.f) s = -1e9f;
        v[u] = s;
        mx = fmaxf(mx, s);
    }
    #pragma unroll
    for (int o = 16; o; o >>= 1) mx = fmaxf(mx, __shfl_xor_sync(~0u, mx, o));
    float sum = 0.f;
    #pragma unroll
    for (int u = 0; u < 16; ++u) { float e = __expf(v[u] - mx); v[u] = e; sum += e; }
    #pragma unroll
    for (int o = 16; o; o >>= 1) sum += __shfl_xor_sync(~0u, sum, o);
    const float inv = 1.f / sum;

    float* ar = g_attn + ((size_t)bt * 8 + hh) * 512;
    #pragma unroll
    for (int u = 0; u < 16; ++u) {
        int nn = lane + 32 * u;
        ar[nn] = v[u] * inv * aS[nn];
    }
}

// ===================== k_agg: aggregation + final projection =====================
// 256 threads: feature e = tid&127, n-half = tid>>7; 8 accumulators for MLP.
__global__ __launch_bounds__(256) void k_agg(
    const float* __restrict__ W2, const float* __restrict__ b2,
    float* __restrict__ out)
{
    __shared__ float atS[8 * 512];
    __shared__ float pacc[256];
    __shared__ float cat[256];
    const int bt = blockIdx.x;
    const int b = bt >> 7, t = bt & 127;
    const int tid = threadIdx.x;
    const int e = tid & 127, half = tid >> 7;

    const float* ab = g_attn + (size_t)bt * 4096;
    for (int q = tid; q < 4096; q += 256) atS[q] = ab[q];
    __syncthreads();

    const float* hb = g_hp + ((size_t)b * 65536 + t) * 128 + e;
    const float* arow = atS + (e >> 4) * 512;

    float a[8] = {0.f, 0.f, 0.f, 0.f, 0.f, 0.f, 0.f, 0.f};
    #pragma unroll 2
    for (int n = half; n < 512; n += 16) {
        #pragma unroll
        for (int u = 0; u < 8; ++u)
            a[u] = fmaf(arow[n + 2 * u], hb[(size_t)(n + 2 * u) * 16384], a[u]);
    }
    pacc[tid] = ((a[0] + a[1]) + (a[2] + a[3])) + ((a[4] + a[5]) + (a[6] + a[7]));
    if (half == 0) cat[128 + e] = hb[0];   // target_h (n == 0)
    __syncthreads();
    if (tid < 128) cat[tid] = pacc[tid] + pacc[128 + tid];
    __syncthreads();

    if (tid < 128) {
        float o = b2[e];
        #pragma unroll 8
        for (int k2 = 0; k2 < 256; ++k2) o = fmaf(cat[k2], W2[k2 * 128 + e], o);
        out[(size_t)bt * 128 + e] = o;
    }
}

// ===================== launch =====================
extern "C" void kernel_launch(void* const* d_in, const int* in_sizes, int n_in,
                              void* d_out, int out_size)
{
    const float* h    = (const float*)d_in[0];
    const float* adj  = (const float*)d_in[1];
    const float* mask = (const float*)d_in[2];
    const float* W1   = (const float*)d_in[3];
    const float* b1   = (const float*)d_in[4];
    const float* Wa   = (const float*)d_in[5];
    const float* ba   = (const float*)d_in[6];
    const float* W2   = (const float*)d_in[7];
    const float* b2   = (const float*)d_in[8];
    float* out = (float*)d_out;

    cudaFuncSetAttribute(k_gemm, cudaFuncAttributeMaxDynamicSharedMemorySize,
                         SMEM_TOTAL);

    k_gemm<<<GRID_GEMM, 256, SMEM_TOTAL>>>(h, W1, b1, Wa);
    k_soft<<<B_ * T_, 256>>>(adj, mask, ba);
    k_agg<<<B_ * T_, 256>>>(W2, b2, out);
}

// round 13
// speedup vs baseline: 1.4130x; 1.1179x over previous
#include <cuda_runtime.h>
#include <cuda_fp16.h>
#include <cstdint>

#define B_ 8
#define N_ 512
#define T_ 128
#define H_ 8

#define NTILES 4096        // tile = 128 rows (all t for one (b,n)) x 128 cols
#define GRID_GEMM 152
#define ROWB 272           // padded row stride in bytes -> conflict-free ldmatrix
#define IMS 34816          // one 128x128 fp16 image = 128*272 bytes

// -------- scratch (device globals: allocation-free) --------
__device__ __half g_hp[(size_t)B_ * N_ * T_ * 128];     // [b][n][t][e]  (fp16, 128 MB)
__device__ float g_sj[(size_t)B_ * N_ * T_ * H_];       // [b][n][t][h]
__device__ float g_s0[B_ * T_ * H_];                    // [b][t][h]
__device__ float g_attn[(size_t)B_ * T_ * H_ * N_];     // [b][t][h][n]

// ---------------- helpers ----------------
__device__ __forceinline__ uint32_t smem_u32(const void* p) {
    uint32_t a;
    asm("{ .reg .u64 t; cvta.to.shared.u64 t, %1; cvt.u32.u64 %0, t; }" : "=r"(a) : "l"(p));
    return a;
}
__device__ __forceinline__ void ldsm4(uint32_t* r, uint32_t addr) {
    asm volatile("ldmatrix.sync.aligned.m8n8.x4.shared.b16 {%0,%1,%2,%3}, [%4];"
                 : "=r"(r[0]), "=r"(r[1]), "=r"(r[2]), "=r"(r[3]) : "r"(addr));
}
__device__ __forceinline__ void mma_f16(float* c, const uint32_t* a,
                                        uint32_t b0, uint32_t b1) {
    asm volatile(
        "mma.sync.aligned.m16n8k16.row.col.f32.f16.f16.f32 "
        "{%0,%1,%2,%3}, {%4,%5,%6,%7}, {%8,%9}, {%0,%1,%2,%3};"
        : "+f"(c[0]), "+f"(c[1]), "+f"(c[2]), "+f"(c[3])
        : "r"(a[0]), "r"(a[1]), "r"(a[2]), "r"(a[3]), "r"(b0), "r"(b1));
}
__device__ __forceinline__ uint32_t pk_h(float a, float b) {  // lo-half=a, hi-half=b
    uint32_t r;
    asm("cvt.rn.f16x2.f32 %0, %1, %2;" : "=r"(r) : "f"(b), "f"(a));
    return r;
}
__device__ __forceinline__ float h_round(float x) {
    return __half2float(__float2half(x));
}

// ===================== k_gemm: persistent mma.sync 2-pass fp16 GEMM =====================
// smem: Whi@0, Wlo@IMS, A[buf]@2*IMS + buf*IMS, b1@4*IMS, Wa@4*IMS+512
#define SM_A     (2 * IMS)
#define SM_B1    (4 * IMS)
#define SM_WA    (4 * IMS + 512)
#define SMEM_TOTAL (4 * IMS + 640)

__global__ __launch_bounds__(256, 1) void k_gemm(
    const float* __restrict__ h, const float* __restrict__ W1,
    const float* __restrict__ b1, const float* __restrict__ Wa)
{
    extern __shared__ char smem[];
    const uint32_t sb = smem_u32(smem);
    const int tid = threadIdx.x, wid = tid >> 5, l = tid & 31;
    const int wr = wid >> 1, wc = wid & 1;     // warp grid 4x2 (rows x cols)

    // ---- one-time: build W^T hi/lo fp16 images in smem directly from W1 ----
    {
        #pragma unroll
        for (int p = 0; p < 16; ++p) {
            int q = tid + p * 256;              // 4096 float4 = 16384 elems
            float4 w4 = reinterpret_cast<const float4*>(W1)[q];
            int k = q >> 5, e4 = (q & 31) << 2; // W1[k][e4..e4+3]
            #pragma unroll
            for (int u = 0; u < 4; ++u) {
                float w = (u == 0) ? w4.x : (u == 1) ? w4.y : (u == 2) ? w4.z : w4.w;
                uint32_t off = (uint32_t)(e4 + u) * ROWB + (uint32_t)k * 2;
                *reinterpret_cast<__half*>(smem + off) = __float2half(w);
                *reinterpret_cast<__half*>(smem + IMS + off) =
                    __float2half(w - h_round(w));
            }
        }
    }
    if (tid < 128) ((float*)(smem + SM_B1))[tid] = b1[tid];
    if (tid < 32)  ((float*)(smem + SM_WA))[tid] = Wa[tid];

    const float* b1s = (const float*)(smem + SM_B1);
    const float* waS = (const float*)(smem + SM_WA);

    // per-lane ldmatrix offsets
    const uint32_t a_lane = (uint32_t)((l & 15) * ROWB + (l >> 4) * 16);
    const uint32_t b_lane = (uint32_t)(((l >> 4) * 8 + (l & 7)) * ROWB + ((l >> 3) & 1) * 16);
    const uint32_t a_warp = (uint32_t)(wr * 32) * ROWB;
    const uint32_t b_warp = (uint32_t)(wc * 64) * ROWB;

    const int tstart = blockIdx.x, tstep = gridDim.x;
    const int nlocal = (NTILES - tstart + tstep - 1) / tstep;

    auto ldg_chunk = [&](int tile, int c, float4* rg) {
        const float4* hg = reinterpret_cast<const float4*>(h + (size_t)tile * 16384);
        #pragma unroll
        for (int p = 0; p < 8; ++p) rg[p] = hg[c * 2048 + tid + p * 256];
    };
    auto sts_chunk = [&](int buf, int c, const float4* rg) {
        char* Ah = smem + SM_A + buf * IMS;
        #pragma unroll
        for (int p = 0; p < 8; ++p) {
            int q = c * 2048 + tid + p * 256;
            int row = q >> 5, k4 = (q & 31) << 2;
            float4 v = rg[p];
            *reinterpret_cast<uint2*>(Ah + row * ROWB + k4 * 2) =
                make_uint2(pk_h(v.x, v.y), pk_h(v.z, v.w));
        }
    };

    float acc[2][8][4];

    auto mma_half = [&](int buf, int ks0) {
        const uint32_t AB = sb + SM_A + buf * IMS;
        const uint32_t BhiB = sb, BloB = sb + IMS;
        #pragma unroll
        for (int ks = 0; ks < 4; ++ks) {
            const uint32_t ko = (uint32_t)(ks0 + ks) * 32;
            uint32_t bh[16], bl[16];
            #pragma unroll
            for (int np = 0; np < 4; ++np) {
                ldsm4(&bh[np * 4], BhiB + b_warp + np * 16 * ROWB + ko + b_lane);
                ldsm4(&bl[np * 4], BloB + b_warp + np * 16 * ROWB + ko + b_lane);
            }
            #pragma unroll
            for (int mt = 0; mt < 2; ++mt) {
                uint32_t ah[4];
                ldsm4(ah, AB + a_warp + mt * 16 * ROWB + ko + a_lane);
                #pragma unroll
                for (int nt = 0; nt < 8; ++nt) {
                    const int bi = (nt >> 1) * 4 + (nt & 1) * 2;
                    mma_f16(acc[mt][nt], ah, bh[bi], bh[bi + 1]);
                    mma_f16(acc[mt][nt], ah, bl[bi], bl[bi + 1]);
                }
            }
        }
    };

    // ---- prologue: stage tile 0 into buf 0 ----
    {
        float4 r0_[8], r1_[8];
        ldg_chunk(tstart, 0, r0_);
        ldg_chunk(tstart, 1, r1_);
        sts_chunk(0, 0, r0_);
        sts_chunk(0, 1, r1_);
    }
    __syncthreads();

    for (int i = 0;; ++i) {
        const int tile = tstart + i * tstep;
        const bool more = (i + 1 < nlocal);
        const int cur = i & 1, nxt = cur ^ 1;

        #pragma unroll
        for (int mt = 0; mt < 2; ++mt)
            #pragma unroll
            for (int nt = 0; nt < 8; ++nt)
                #pragma unroll
                for (int j = 0; j < 4; ++j) acc[mt][nt][j] = 0.f;

        float4 rg[8];
        if (more) ldg_chunk(tile + tstep, 0, rg);
        mma_half(cur, 0);
        if (more) { sts_chunk(nxt, 0, rg); ldg_chunk(tile + tstep, 1, rg); }
        mma_half(cur, 4);
        if (more) sts_chunk(nxt, 1, rg);

        // ---- epilogue (hp stored as fp16) ----
        __half* hpB = g_hp + (size_t)tile * 16384;
        const float wd0e = waS[16 + (l & 3) * 2], wd1e = waS[17 + (l & 3) * 2];
        const float wd0o = waS[24 + (l & 3) * 2], wd1o = waS[25 + (l & 3) * 2];
        const bool is_n0 = ((tile & (N_ - 1)) == 0);

        #pragma unroll
        for (int mt = 0; mt < 2; ++mt) {
            const int r0 = wr * 32 + mt * 16 + (l >> 2), r1 = r0 + 8;
            float p0[4] = {0, 0, 0, 0}, p1[4] = {0, 0, 0, 0};
            #pragma unroll
            for (int nt = 0; nt < 8; ++nt) {
                const int col = wc * 64 + nt * 8 + (l & 3) * 2;
                const float bv0 = b1s[col], bv1 = b1s[col + 1];
                const float v00 = acc[mt][nt][0] + bv0, v01 = acc[mt][nt][1] + bv1;
                const float v10 = acc[mt][nt][2] + bv0, v11 = acc[mt][nt][3] + bv1;
                *reinterpret_cast<uint32_t*>(&hpB[(size_t)r0 * 128 + col]) = pk_h(v00, v01);
                *reinterpret_cast<uint32_t*>(&hpB[(size_t)r1 * 128 + col]) = pk_h(v10, v11);
                const float w0 = (nt & 1) ? wd0o : wd0e;
                const float w1 = (nt & 1) ? wd1o : wd1e;
                p0[nt >> 1] += v00 * w0 + v01 * w1;
                p1[nt >> 1] += v10 * w0 + v11 * w1;
            }
            #pragma unroll
            for (int h4 = 0; h4 < 4; ++h4) {
                p0[h4] += __shfl_xor_sync(~0u, p0[h4], 1);
                p0[h4] += __shfl_xor_sync(~0u, p0[h4], 2);
                p1[h4] += __shfl_xor_sync(~0u, p1[h4], 1);
                p1[h4] += __shfl_xor_sync(~0u, p1[h4], 2);
            }
            if ((l & 3) == 0) {
                *reinterpret_cast<float4*>(&g_sj[((size_t)tile * 128 + r0) * 8 + wc * 4]) =
                    make_float4(p0[0], p0[1], p0[2], p0[3]);
                *reinterpret_cast<float4*>(&g_sj[((size_t)tile * 128 + r1) * 8 + wc * 4]) =
                    make_float4(p1[0], p1[1], p1[2], p1[3]);
            }
            if (is_n0) {
                const float ws0e = waS[(l & 3) * 2], ws1e = waS[1 + (l & 3) * 2];
                const float ws0o = waS[8 + (l & 3) * 2], ws1o = waS[9 + (l & 3) * 2];
                float q0[4] = {0, 0, 0, 0}, q1[4] = {0, 0, 0, 0};
                #pragma unroll
                for (int nt = 0; nt < 8; ++nt) {
                    const int col = wc * 64 + nt * 8 + (l & 3) * 2;
                    const float bv0 = b1s[col], bv1 = b1s[col + 1];
                    const float w0 = (nt & 1) ? ws0o : ws0e;
                    const float w1 = (nt & 1) ? ws1o : ws1e;
                    q0[nt >> 1] += (acc[mt][nt][0] + bv0) * w0 + (acc[mt][nt][1] + bv1) * w1;
                    q1[nt >> 1] += (acc[mt][nt][2] + bv0) * w0 + (acc[mt][nt][3] + bv1) * w1;
                }
                #pragma unroll
                for (int h4 = 0; h4 < 4; ++h4) {
                    q0[h4] += __shfl_xor_sync(~0u, q0[h4], 1);
                    q0[h4] += __shfl_xor_sync(~0u, q0[h4], 2);
                    q1[h4] += __shfl_xor_sync(~0u, q1[h4], 1);
                    q1[h4] += __shfl_xor_sync(~0u, q1[h4], 2);
                }
                if ((l & 3) == 0) {
                    const int b = tile >> 9;
                    *reinterpret_cast<float4*>(&g_s0[(b * 128 + r0) * 8 + wc * 4]) =
                        make_float4(q0[0], q0[1], q0[2], q0[3]);
                    *reinterpret_cast<float4*>(&g_s0[(b * 128 + r1) * 8 + wc * 4]) =
                        make_float4(q1[0], q1[1], q1[2], q1[3]);
                }
            }
        }
        __syncthreads();
        if (!more) break;
    }
}

// ===================== k_soft: masked softmax * adj-scale =====================
__global__ __launch_bounds__(256) void k_soft(
    const float* __restrict__ adj, const float* __restrict__ mask,
    const float* __restrict__ ba)
{
    __shared__ float aS[512];
    __shared__ float mS[512];
    __shared__ float sS[512 * 9];
    const int bt = blockIdx.x;
    const int b = bt >> 7, t = bt & 127;
    const int tid = threadIdx.x;

    for (int q = tid; q < 512; q += 256) {
        float av = adj[(size_t)bt * 512 + q];
        float mv = mask[((size_t)b * 512 + q) * 128 + t];
        av = (av == 0.f) ? 1e9f : av;
        av = (mv > 0.f) ? (1.f / av) : av;
        aS[q] = av;
        mS[q] = mv;
    }
    for (int q = tid; q < 4096; q += 256) {
        int n = q >> 3, hv = q & 7;
        sS[n * 9 + hv] = g_sj[(size_t)b * 524288 + (size_t)n * 1024 + t * 8 + hv];
    }
    __syncthreads();

    const int hh = tid >> 5, lane = tid & 31;
    const float s0v = g_s0[bt * 8 + hh] + ba[0];

    float v[16];
    float mx = -3.4e38f;
    #pragma unroll
    for (int u = 0; u < 16; ++u) {
        int nn = lane + 32 * u;
        float s = sS[nn * 9 + hh] + s0v;
        if (mS[nn] == 0.f) s = -1e9f;
        v[u] = s;
        mx = fmaxf(mx, s);
    }
    #pragma unroll
    for (int o = 16; o; o >>= 1) mx = fmaxf(mx, __shfl_xor_sync(~0u, mx, o));
    float sum = 0.f;
    #pragma unroll
    for (int u = 0; u < 16; ++u) { float e = __expf(v[u] - mx); v[u] = e; sum += e; }
    #pragma unroll
    for (int o = 16; o; o >>= 1) sum += __shfl_xor_sync(~0u, sum, o);
    const float inv = 1.f / sum;

    float* ar = g_attn + ((size_t)bt * 8 + hh) * 512;
    #pragma unroll
    for (int u = 0; u < 16; ++u) {
        int nn = lane + 32 * u;
        ar[nn] = v[u] * inv * aS[nn];
    }
}

// ===================== k_agg: aggregation + final projection =====================
// 256 threads: feature e = tid&127, n-half = tid>>7; 8 accumulators for MLP.
__global__ __launch_bounds__(256) void k_agg(
    const float* __restrict__ W2, const float* __restrict__ b2,
    float* __restrict__ out)
{
    __shared__ float atS[8 * 512];
    __shared__ float pacc[256];
    __shared__ float cat[256];
    const int bt = blockIdx.x;
    const int b = bt >> 7, t = bt & 127;
    const int tid = threadIdx.x;
    const int e = tid & 127, half = tid >> 7;

    const float* ab = g_attn + (size_t)bt * 4096;
    for (int q = tid; q < 4096; q += 256) atS[q] = ab[q];
    __syncthreads();

    const __half* hb = g_hp + ((size_t)b * 65536 + t) * 128 + e;
    const float* arow = atS + (e >> 4) * 512;

    float a[8] = {0.f, 0.f, 0.f, 0.f, 0.f, 0.f, 0.f, 0.f};
    #pragma unroll 2
    for (int n = half; n < 512; n += 16) {
        #pragma unroll
        for (int u = 0; u < 8; ++u)
            a[u] = fmaf(arow[n + 2 * u],
                        __half2float(hb[(size_t)(n + 2 * u) * 16384]), a[u]);
    }
    pacc[tid] = ((a[0] + a[1]) + (a[2] + a[3])) + ((a[4] + a[5]) + (a[6] + a[7]));
    if (half == 0) cat[128 + e] = __half2float(hb[0]);   // target_h (n == 0)
    __syncthreads();
    if (tid < 128) cat[tid] = pacc[tid] + pacc[128 + tid];
    __syncthreads();

    if (tid < 128) {
        float o = b2[e];
        #pragma unroll 8
        for (int k2 = 0; k2 < 256; ++k2) o = fmaf(cat[k2], W2[k2 * 128 + e], o);
        out[(size_t)bt * 128 + e] = o;
    }
}

// ===================== launch =====================
extern "C" void kernel_launch(void* const* d_in, const int* in_sizes, int n_in,
                              void* d_out, int out_size)
{
    const float* h    = (const float*)d_in[0];
    const float* adj  = (const float*)d_in[1];
    const float* mask = (const float*)d_in[2];
    const float* W1   = (const float*)d_in[3];
    const float* b1   = (const float*)d_in[4];
    const float* Wa   = (const float*)d_in[5];
    const float* ba   = (const float*)d_in[6];
    const float* W2   = (const float*)d_in[7];
    const float* b2   = (const float*)d_in[8];
    float* out = (float*)d_out;

    cudaFuncSetAttribute(k_gemm, cudaFuncAttributeMaxDynamicSharedMemorySize,
                         SMEM_TOTAL);

    k_gemm<<<GRID_GEMM, 256, SMEM_TOTAL>>>(h, W1, b1, Wa);
    k_soft<<<B_ * T_, 256>>>(adj, mask, ba);
    k_agg<<<B_ * T_, 256>>>(W2, b2, out);
}